// round 15
// baseline (speedup 1.0000x reference)
#include <cuda_runtime.h>
#include <math.h>

#define IMG   112
#define CCH   192
#define GIMG  8                        // images per L2 chunk (77 MB < 126 MB L2)
#define NGRP  (32/GIMG)                // 4 groups
#define PAIRS_G (GIMG*IMG*IMG/2)       // 50176 pixel-pairs per group
#define TW    16
#define TH    4
#define HALO  3
#define HDW   (TW + 2*HALO)            // 22
#define HDH   (TH + 2*HALO)            // 10
#define NHP   (HDW*HDH)                // 220
#define NT    256
#define NW    (NT/32)                  // 8
#define F4    (CCH/4)                  // 48
#define GRID  (148*8)                  // 1184 blocks, all co-resident
#define TPX   (IMG/TW)                 // 7
#define TPY   (IMG/TH)                 // 28
#define TILES_G (GIMG*TPX*TPY)         // 1568 tiles per group

__device__ float g_pooled[32*IMG*IMG * 2];   // 3.2 MB
__device__ volatile unsigned g_bar;
__device__ unsigned g_tile[NGRP];

__device__ __forceinline__ float hsum(float4 v) { return (v.x + v.y) + (v.z + v.w); }
__device__ __forceinline__ float hmax(float4 v) { return fmaxf(fmaxf(v.x, v.y), fmaxf(v.z, v.w)); }

__global__ void init_kernel()
{
    g_bar = 0u;
    #pragma unroll
    for (int i = 0; i < NGRP; i++) g_tile[i] = 0u;
}

__device__ __forceinline__ void grid_barrier(int tid, unsigned target)
{
    __syncthreads();
    if (tid == 0) {
        __threadfence();
        atomicAdd((unsigned*)&g_bar, 1u);
        while (g_bar < target) { }
    }
    __syncthreads();
    __threadfence();
}

__global__ __launch_bounds__(NT, 8)
void persist_kernel(const float* __restrict__ x,
                    const float* __restrict__ w,
                    float* __restrict__ out)
{
    __shared__ float s_avg[NHP];
    __shared__ float s_max[NHP];
    __shared__ float s_att[TW*TH];
    __shared__ float s_w[98];
    __shared__ int   s_tile;

    const int tid  = threadIdx.x;
    const int lane = tid & 31;

    if (tid < 98) s_w[tid] = w[tid];

    unsigned nbar = 0;

    for (int g = 0; g < NGRP; g++) {
        // ===== Phase R: reduce group g (default cache policy -> chunk into L2) =====
        {
            const int gwarp  = blockIdx.x * NW + (tid >> 5);
            const int nwarps = GRID * NW;            // 9472
            const int p0 = g * PAIRS_G, p1 = p0 + PAIRS_G;

            for (int pair = p0 + gwarp; pair < p1; pair += nwarps) {
                const float4* p = reinterpret_cast<const float4*>(x + (size_t)pair * 2 * CCH);
                float4 a0 = p[lane];          // pixel 0
                float4 a1 = p[32 + lane];     // split halves
                float4 a2 = p[64 + lane];     // pixel 1

                float s0 = hsum(a0), m0 = hmax(a0);
                float s1 = hsum(a2), m1 = hmax(a2);
                float sm = hsum(a1), mm = hmax(a1);
                if (lane < 16) { s0 += sm; m0 = fmaxf(m0, mm); }
                else           { s1 += sm; m1 = fmaxf(m1, mm); }

                #pragma unroll
                for (int o = 16; o > 0; o >>= 1) {
                    s0 += __shfl_xor_sync(0xffffffffu, s0, o);
                    s1 += __shfl_xor_sync(0xffffffffu, s1, o);
                    m0  = fmaxf(m0, __shfl_xor_sync(0xffffffffu, m0, o));
                    m1  = fmaxf(m1, __shfl_xor_sync(0xffffffffu, m1, o));
                }
                if (lane == 0) {
                    float4 r = make_float4(s0 * (1.0f / CCH), m0, s1 * (1.0f / CCH), m1);
                    *reinterpret_cast<float4*>(&g_pooled[(size_t)pair * 4]) = r;
                }
            }
        }

        nbar += GRID;
        grid_barrier(tid, nbar);

        // ===== Phase A: apply group g off a dynamic queue (x reads hit L2) =====
        for (;;) {
            if (tid == 0) s_tile = (int)atomicAdd(&g_tile[g], 1u);
            __syncthreads();
            int t = s_tile;
            if (t >= TILES_G) break;

            int b   = g * GIMG + t / (TPX*TPY);
            int tr  = t % (TPX*TPY);
            int ty0 = (tr / TPX) * TH;
            int tx0 = (tr % TPX) * TW;

            for (int p = tid; p < NHP; p += NT) {
                int hy = ty0 + p / HDW - HALO;
                int wx = tx0 + p % HDW - HALO;
                float a = 0.f, m = 0.f;
                if (hy >= 0 && hy < IMG && wx >= 0 && wx < IMG) {
                    size_t pix = ((size_t)b * IMG + hy) * IMG + wx;
                    float2 r = *reinterpret_cast<const float2*>(&g_pooled[pix * 2]);
                    a = r.x; m = r.y;
                }
                s_avg[p] = a;
                s_max[p] = m;
            }
            __syncthreads();

            if (tid < TW*TH) {
                int oy = tid / TW, ox = tid % TW;
                float acc = 0.f;
                #pragma unroll
                for (int kh = 0; kh < 7; kh++) {
                    #pragma unroll
                    for (int kw = 0; kw < 7; kw++) {
                        int p = (oy + kh) * HDW + (ox + kw);
                        acc = fmaf(s_avg[p], s_w[(kh*7 + kw)*2 + 0], acc);
                        acc = fmaf(s_max[p], s_w[(kh*7 + kw)*2 + 1], acc);
                    }
                }
                s_att[tid] = 1.0f / (1.0f + __expf(-acc));
            }
            __syncthreads();

            // total4 = 16*4*48 = 3072 = 4 * (NT*3)  -> exact unroll-3
            const int total4 = TW*TH*F4;
            #pragma unroll 1
            for (int k = tid; k < total4; k += NT*3) {
                float4 v[3]; float a[3]; size_t gg[3];
                #pragma unroll
                for (int u = 0; u < 3; u++) {
                    int kk = k + u*NT;
                    int pt = kk / F4;
                    int c4 = kk - pt * F4;
                    int oy = pt / TW, ox = pt - oy * TW;
                    gg[u] = (((size_t)b * IMG + (ty0 + oy)) * IMG + (tx0 + ox)) * CCH + (size_t)c4 * 4;
                    v[u] = *reinterpret_cast<const float4*>(x + gg[u]);   // L2 hit
                    a[u] = s_att[pt];
                }
                #pragma unroll
                for (int u = 0; u < 3; u++) {
                    float4 r = v[u]; float s = a[u];
                    r.x *= s; r.y *= s; r.z *= s; r.w *= s;
                    __stcs(reinterpret_cast<float4*>(out + gg[u]), r);    // evict-first
                }
            }
            __syncthreads();
        }

        if (g < NGRP - 1) {
            nbar += GRID;
            grid_barrier(tid, nbar);   // keep phases clean: no mixed chunk flows
        }
    }
}

extern "C" void kernel_launch(void* const* d_in, const int* in_sizes, int n_in,
                              void* d_out, int out_size)
{
    const float* x = (const float*)d_in[0];
    const float* w = (const float*)d_in[1];
    float* out = (float*)d_out;

    init_kernel<<<1, 1>>>();
    persist_kernel<<<GRID, NT>>>(x, w, out);
}

// round 16
// speedup vs baseline: 1.1556x; 1.1556x over previous
#include <cuda_runtime.h>
#include <math.h>

#define IMG   112
#define CCH   192
#define NPIX  (32*IMG*IMG)         // 401408 pixels
#define NPAIR (NPIX/2)             // 200704
#define TW    28
#define TH    4
#define HALO  3
#define HDW   (TW + 2*HALO)        // 34
#define HDH   (TH + 2*HALO)        // 10
#define NHP   (HDW*HDH)            // 340
#define NT    256
#define NW    (NT/32)              // 8
#define F4    (CCH/4)              // 48
#define GRID  (148*8)              // 1184 blocks, all co-resident at occ 8
#define NTILES (32*(IMG/TW)*(IMG/TH))  // 3584 apply tiles

// pooled[pix*2+0]=avg, [pix*2+1]=max  (3.2 MB, L2-resident)
__device__ float g_pooled[NPIX * 2];
// self-resetting sync state (all return to initial values by kernel end)
__device__ unsigned g_bar  = 0;
__device__ volatile unsigned g_gen = 0;
__device__ unsigned g_tile = 0;
__device__ unsigned g_done = 0;

__device__ __forceinline__ float hsum(float4 v) { return (v.x + v.y) + (v.z + v.w); }
__device__ __forceinline__ float hmax(float4 v) { return fmaxf(fmaxf(v.x, v.y), fmaxf(v.z, v.w)); }

// Generation-based grid barrier: last arriver resets the counter and bumps
// the generation; everyone else spins on the generation. Self-resetting.
__device__ __forceinline__ void grid_barrier(int tid)
{
    __syncthreads();
    if (tid == 0) {
        __threadfence();
        unsigned gen = g_gen;
        unsigned arr = atomicAdd(&g_bar, 1u);
        if (arr == GRID - 1u) {
            g_bar = 0u;
            __threadfence();
            g_gen = gen + 1u;
        } else {
            while (g_gen == gen) { }
        }
    }
    __syncthreads();
    __threadfence();
}

__global__ __launch_bounds__(NT, 8)
void persist_kernel(const float* __restrict__ x,
                    const float* __restrict__ w,
                    float* __restrict__ out)
{
    __shared__ float s_avg[NHP];
    __shared__ float s_max[NHP];
    __shared__ float s_att[TW*TH];
    __shared__ float s_w[98];
    __shared__ int   s_tile;

    const int tid  = threadIdx.x;
    const int lane = tid & 31;

    if (tid < 98) s_w[tid] = w[tid];

    // ================= Phase 1: channel avg/max, 2 pixels per warp =================
    {
        const int gwarp  = blockIdx.x * NW + (tid >> 5);
        const int nwarps = GRID * NW;            // 9472

        for (int pair = gwarp; pair < NPAIR; pair += nwarps) {
            const float4* p = reinterpret_cast<const float4*>(x + (size_t)pair * 2 * CCH);
            float4 a0 = __ldcs(p + lane);        // pixel 0
            float4 a1 = __ldcs(p + 32 + lane);   // split
            float4 a2 = __ldcs(p + 64 + lane);   // pixel 1

            float s0 = hsum(a0), m0 = hmax(a0);
            float s1 = hsum(a2), m1 = hmax(a2);
            float sm = hsum(a1), mm = hmax(a1);
            if (lane < 16) { s0 += sm; m0 = fmaxf(m0, mm); }
            else           { s1 += sm; m1 = fmaxf(m1, mm); }

            #pragma unroll
            for (int o = 16; o > 0; o >>= 1) {
                s0 += __shfl_xor_sync(0xffffffffu, s0, o);
                s1 += __shfl_xor_sync(0xffffffffu, s1, o);
                m0  = fmaxf(m0, __shfl_xor_sync(0xffffffffu, m0, o));
                m1  = fmaxf(m1, __shfl_xor_sync(0xffffffffu, m1, o));
            }
            if (lane == 0) {
                float4 r = make_float4(s0 * (1.0f / CCH), m0, s1 * (1.0f / CCH), m1);
                *reinterpret_cast<float4*>(&g_pooled[(size_t)pair * 4]) = r;
            }
        }
    }

    // ================= Grid barrier (all 1184 blocks co-resident) =================
    grid_barrier(tid);

    // ================= Phase 2: apply tiles off a dynamic queue =================
    const int TPX = IMG / TW;                // 4
    const int TPY = IMG / TH;                // 28

    for (;;) {
        if (tid == 0) s_tile = (int)atomicAdd(&g_tile, 1u);
        __syncthreads();
        int t = s_tile;
        if (t >= NTILES) break;

        int b   = t / (TPX*TPY);
        int tr  = t % (TPX*TPY);
        int ty0 = (tr / TPX) * TH;
        int tx0 = (tr % TPX) * TW;

        // halo of pooled (L2-hot)
        for (int p = tid; p < NHP; p += NT) {
            int hy = ty0 + p / HDW - HALO;
            int wx = tx0 + p % HDW - HALO;
            float a = 0.f, m = 0.f;
            if (hy >= 0 && hy < IMG && wx >= 0 && wx < IMG) {
                size_t pix = ((size_t)b * IMG + hy) * IMG + wx;
                float2 r = *reinterpret_cast<const float2*>(&g_pooled[pix * 2]);
                a = r.x; m = r.y;
            }
            s_avg[p] = a;
            s_max[p] = m;
        }
        __syncthreads();

        // 7x7 conv (cross-correlation) + sigmoid
        if (tid < TW*TH) {
            int oy = tid / TW, ox = tid % TW;
            float acc = 0.f;
            #pragma unroll
            for (int kh = 0; kh < 7; kh++) {
                #pragma unroll
                for (int kw = 0; kw < 7; kw++) {
                    int p = (oy + kh) * HDW + (ox + kw);
                    acc = fmaf(s_avg[p], s_w[(kh*7 + kw)*2 + 0], acc);
                    acc = fmaf(s_max[p], s_w[(kh*7 + kw)*2 + 1], acc);
                }
            }
            s_att[tid] = 1.0f / (1.0f + __expf(-acc));
        }
        __syncthreads();

        // out = x * att, float4 streaming, exact unroll-3
        // total4 = 28*4*48 = 5376 = 7 * (NT*3)
        const int total4 = TW*TH*F4;
        #pragma unroll 1
        for (int k = tid; k < total4; k += NT*3) {
            float4 v[3]; float a[3]; size_t g[3];
            #pragma unroll
            for (int u = 0; u < 3; u++) {
                int kk = k + u*NT;
                int pt = kk / F4;
                int c4 = kk - pt * F4;
                int oy = pt / TW, ox = pt - oy * TW;
                g[u] = (((size_t)b * IMG + (ty0 + oy)) * IMG + (tx0 + ox)) * CCH + (size_t)c4 * 4;
                v[u] = __ldcs(reinterpret_cast<const float4*>(x + g[u]));
                a[u] = s_att[pt];
            }
            #pragma unroll
            for (int u = 0; u < 3; u++) {
                float4 r = v[u]; float s = a[u];
                r.x *= s; r.y *= s; r.z *= s; r.w *= s;
                __stcs(reinterpret_cast<float4*>(out + g[u]), r);
            }
        }
        __syncthreads();   // protect smem before next tile
    }

    // ================= Self-reset the queue for the next graph replay =================
    if (tid == 0) {
        unsigned d = atomicAdd(&g_done, 1u);
        if (d == GRID - 1u) {      // last block out resets all queue state
            g_tile = 0u;
            g_done = 0u;
            __threadfence();
        }
    }
}

extern "C" void kernel_launch(void* const* d_in, const int* in_sizes, int n_in,
                              void* d_out, int out_size)
{
    const float* x = (const float*)d_in[0];
    const float* w = (const float*)d_in[1];
    float* out = (float*)d_out;

    persist_kernel<<<GRID, NT>>>(x, w, out);   // single launch, self-resetting state
}